// round 1
// baseline (speedup 1.0000x reference)
#include <cuda_runtime.h>
#include <math.h>

#define TT 64
#define BB 256
#define EMBD 1024
#define ADIM 6
#define STOCHD 64
#define HIDD 512
#define FEATD 512
#define STATED 576           // HIDD + STOCHD
#define TBD (TT*BB)          // 16384
#define LOG2PI_F 1.837877066409345483560659472811f

// ------------------------- static device scratch -------------------------
__device__ float g_hs[TBD*HIDD];          // next_h per step
__device__ float g_ss[TBD*STOCHD];        // s_{t+1} per step
__device__ float g_qmu[TBD*STOCHD];
__device__ float g_qstd[TBD*STOCHD];
__device__ float g_xcat[BB*(STOCHD+ADIM)];
__device__ float g_gi[BB*3*HIDD];
__device__ float g_gh[BB*3*HIDD];
__device__ float g_postcat[BB*(HIDD+EMBD)];
__device__ float g_h1[BB*FEATD];
__device__ float g_h2[BB*FEATD];
__device__ float g_qraw[BB*2*STOCHD];
__device__ float g_zerobuf[BB*HIDD];      // zero-initialized, never written
__device__ float g_part[2*1024*1024];     // split-K partials
__device__ float g_prev[TBD*STATED];
__device__ float g_states[TBD*STATED];
__device__ float g_big1[TBD*FEATD];
__device__ float g_big2[TBD*FEATD];
__device__ float g_preemb[TBD*EMBD];
__device__ float g_priorin[TBD*(HIDD+EMBD)];
__device__ float g_praw[TBD*2*STOCHD];
__device__ float g_embmu[TBD*EMBD];
__device__ double g_acc[3];

// ------------------------- device math helpers -------------------------
__device__ __forceinline__ float softplusf(float x) {
    return fmaxf(x, 0.f) + log1pf(expf(-fabsf(x)));
}
__device__ __forceinline__ float sigmoidf_(float x) {
    return 1.f / (1.f + expf(-x));
}
template<int ACTF>
__device__ __forceinline__ float actf(float v) {
    if (ACTF == 1) return v > 0.f ? v : expm1f(v);
    return v;
}

// ------------------------- GEMM: 64x64 tile (direct, bias+act) -------------------------
// C[M,N] = act(A[M,K] @ W[N,K]^T + bias)
template<int ACTF>
__global__ __launch_bounds__(256) void sgemm64(
    const float* __restrict__ A, const float* __restrict__ W,
    const float* __restrict__ bias, float* __restrict__ C,
    int M, int N, int K)
{
    __shared__ float As[16][65];
    __shared__ float Bs[16][65];
    int tid = threadIdx.x;
    int tx = tid & 15, ty = tid >> 4;
    int row0 = blockIdx.y * 64, col0 = blockIdx.x * 64;
    float acc[4][4];
#pragma unroll
    for (int i = 0; i < 4; i++)
#pragma unroll
        for (int j = 0; j < 4; j++) acc[i][j] = 0.f;

    for (int k0 = 0; k0 < K; k0 += 16) {
#pragma unroll
        for (int i = 0; i < 4; i++) {
            int e = tid + i * 256;
            int m = e >> 4, kk = e & 15;
            int gm = row0 + m, gk = k0 + kk;
            As[kk][m] = (gm < M && gk < K) ? A[gm * K + gk] : 0.f;
            int gn = col0 + m;
            Bs[kk][m] = (gn < N && gk < K) ? W[gn * K + gk] : 0.f;
        }
        __syncthreads();
#pragma unroll
        for (int kk = 0; kk < 16; kk++) {
            float a[4], b[4];
#pragma unroll
            for (int i = 0; i < 4; i++) a[i] = As[kk][ty * 4 + i];
#pragma unroll
            for (int j = 0; j < 4; j++) b[j] = Bs[kk][tx * 4 + j];
#pragma unroll
            for (int i = 0; i < 4; i++)
#pragma unroll
                for (int j = 0; j < 4; j++) acc[i][j] = fmaf(a[i], b[j], acc[i][j]);
        }
        __syncthreads();
    }
#pragma unroll
    for (int i = 0; i < 4; i++) {
        int gm = row0 + ty * 4 + i;
        if (gm >= M) continue;
#pragma unroll
        for (int j = 0; j < 4; j++) {
            int gn = col0 + tx * 4 + j;
            if (gn < N) C[gm * N + gn] = actf<ACTF>(acc[i][j] + bias[gn]);
        }
    }
}

// ------------------------- GEMM: 64x64 tile, split-K partials -------------------------
__global__ __launch_bounds__(256) void sgemm64_part(
    const float* __restrict__ A, const float* __restrict__ W,
    float* __restrict__ part, int M, int N, int K, int Kc)
{
    __shared__ float As[16][65];
    __shared__ float Bs[16][65];
    int tid = threadIdx.x;
    int tx = tid & 15, ty = tid >> 4;
    int row0 = blockIdx.y * 64, col0 = blockIdx.x * 64;
    int kstart = blockIdx.z * Kc;
    int kend = kstart + Kc; if (kend > K) kend = K;
    float acc[4][4];
#pragma unroll
    for (int i = 0; i < 4; i++)
#pragma unroll
        for (int j = 0; j < 4; j++) acc[i][j] = 0.f;

    for (int k0 = kstart; k0 < kend; k0 += 16) {
#pragma unroll
        for (int i = 0; i < 4; i++) {
            int e = tid + i * 256;
            int m = e >> 4, kk = e & 15;
            int gm = row0 + m, gk = k0 + kk;
            As[kk][m] = (gm < M && gk < kend) ? A[gm * K + gk] : 0.f;
            int gn = col0 + m;
            Bs[kk][m] = (gn < N && gk < kend) ? W[gn * K + gk] : 0.f;
        }
        __syncthreads();
#pragma unroll
        for (int kk = 0; kk < 16; kk++) {
            float a[4], b[4];
#pragma unroll
            for (int i = 0; i < 4; i++) a[i] = As[kk][ty * 4 + i];
#pragma unroll
            for (int j = 0; j < 4; j++) b[j] = Bs[kk][tx * 4 + j];
#pragma unroll
            for (int i = 0; i < 4; i++)
#pragma unroll
                for (int j = 0; j < 4; j++) acc[i][j] = fmaf(a[i], b[j], acc[i][j]);
        }
        __syncthreads();
    }
    float* dst = part + (size_t)blockIdx.z * M * N;
#pragma unroll
    for (int i = 0; i < 4; i++) {
        int gm = row0 + ty * 4 + i;
        if (gm >= M) continue;
#pragma unroll
        for (int j = 0; j < 4; j++) {
            int gn = col0 + tx * 4 + j;
            if (gn < N) dst[gm * N + gn] = acc[i][j];
        }
    }
}

template<int ACTF>
__global__ void combine_k(const float* __restrict__ part, const float* __restrict__ bias,
                          float* __restrict__ C, int M, int N, int S)
{
    int total = M * N;
    for (int idx = blockIdx.x * blockDim.x + threadIdx.x; idx < total;
         idx += gridDim.x * blockDim.x) {
        float s = 0.f;
        for (int z = 0; z < S; z++) s += part[(size_t)z * total + idx];
        int col = idx % N;
        C[idx] = actf<ACTF>(s + bias[col]);
    }
}

// ------------------------- GEMM: 128x128 tile (batched passes) -------------------------
// Assumes M%128==0, N%128==0, K%16==0 (true for all batched calls).
template<int ACTF>
__global__ __launch_bounds__(256) void sgemm128(
    const float* __restrict__ A, const float* __restrict__ W,
    const float* __restrict__ bias, float* __restrict__ C,
    int M, int N, int K)
{
    __shared__ float As[16][129];
    __shared__ float Bs[16][129];
    int tid = threadIdx.x;
    int tx = tid & 15, ty = tid >> 4;
    int row0 = blockIdx.y * 128, col0 = blockIdx.x * 128;
    float acc[8][8];
#pragma unroll
    for (int i = 0; i < 8; i++)
#pragma unroll
        for (int j = 0; j < 8; j++) acc[i][j] = 0.f;

    for (int k0 = 0; k0 < K; k0 += 16) {
#pragma unroll
        for (int i = 0; i < 8; i++) {
            int e = tid + i * 256;           // 2048 elements
            int m = e >> 4, kk = e & 15;
            As[kk][m] = A[(size_t)(row0 + m) * K + k0 + kk];
            Bs[kk][m] = W[(size_t)(col0 + m) * K + k0 + kk];
        }
        __syncthreads();
#pragma unroll
        for (int kk = 0; kk < 16; kk++) {
            float a[8], b[8];
#pragma unroll
            for (int i = 0; i < 8; i++) a[i] = As[kk][ty * 8 + i];
#pragma unroll
            for (int j = 0; j < 8; j++) b[j] = Bs[kk][tx * 8 + j];
#pragma unroll
            for (int i = 0; i < 8; i++)
#pragma unroll
                for (int j = 0; j < 8; j++) acc[i][j] = fmaf(a[i], b[j], acc[i][j]);
        }
        __syncthreads();
    }
#pragma unroll
    for (int i = 0; i < 8; i++) {
        int gm = row0 + ty * 8 + i;
#pragma unroll
        for (int j = 0; j < 8; j++) {
            int gn = col0 + tx * 8 + j;
            C[(size_t)gm * N + gn] = actf<ACTF>(acc[i][j] + bias[gn]);
        }
    }
}

// ------------------------- elementwise kernels -------------------------
__global__ void concat2_k(const float* __restrict__ A, int KA,
                          const float* __restrict__ Bm, int KB,
                          float* __restrict__ out, int M)
{
    int K = KA + KB;
    long total = (long)M * K;
    for (long idx = blockIdx.x * (long)blockDim.x + threadIdx.x; idx < total;
         idx += (long)gridDim.x * blockDim.x) {
        int r = (int)(idx / K), c = (int)(idx % K);
        out[idx] = (c < KA) ? A[(long)r * KA + c] : Bm[(long)r * KB + (c - KA)];
    }
}

__global__ void gru_gates_k(const float* __restrict__ gi, const float* __restrict__ gh,
                            const float* __restrict__ hprev, float* __restrict__ hnext)
{
    int idx = blockIdx.x * blockDim.x + threadIdx.x;
    if (idx >= BB * HIDD) return;
    int b = idx / HIDD, j = idx % HIDD;
    const float* gib = gi + (size_t)b * 3 * HIDD;
    const float* ghb = gh + (size_t)b * 3 * HIDD;
    float ir = gib[j],            hr = ghb[j];
    float iz = gib[HIDD + j],     hz = ghb[HIDD + j];
    float inn = gib[2*HIDD + j],  hn = ghb[2*HIDD + j];
    float r = sigmoidf_(ir + hr);
    float z = sigmoidf_(iz + hz);
    float n = tanhf(inn + r * hn);
    hnext[idx] = (1.f - z) * n + z * hprev[idx];
}

__global__ void sample_k(const float* __restrict__ qraw, const float* __restrict__ eps_t,
                         float* __restrict__ qmu_t, float* __restrict__ qstd_t,
                         float* __restrict__ s_out)
{
    int idx = blockIdx.x * blockDim.x + threadIdx.x;
    if (idx >= BB * STOCHD) return;
    int b = idx / STOCHD, i = idx % STOCHD;
    float mu = qraw[(size_t)b * 2 * STOCHD + i];
    float sr = qraw[(size_t)b * 2 * STOCHD + STOCHD + i];
    float sd = softplusf(sr) + 1e-4f;
    qmu_t[idx]  = mu;
    qstd_t[idx] = sd;
    s_out[idx]  = mu + sd * eps_t[idx];
}

__global__ void build_prev_k(const float* __restrict__ hs, const float* __restrict__ ss,
                             float* __restrict__ out)
{
    long total = (long)TBD * STATED;
    for (long idx = blockIdx.x * (long)blockDim.x + threadIdx.x; idx < total;
         idx += (long)gridDim.x * blockDim.x) {
        int r = (int)(idx / STATED), c = (int)(idx % STATED);
        int t = r / BB, b = r % BB;
        float v = 0.f;
        if (t > 0) {
            int rp = (t - 1) * BB + b;
            v = (c < HIDD) ? hs[(size_t)rp * HIDD + c] : ss[(size_t)rp * STOCHD + (c - HIDD)];
        }
        out[idx] = v;
    }
}

__global__ void build_states_k(const float* __restrict__ hs, const float* __restrict__ ss,
                               float* __restrict__ out)
{
    long total = (long)TBD * STATED;
    for (long idx = blockIdx.x * (long)blockDim.x + threadIdx.x; idx < total;
         idx += (long)gridDim.x * blockDim.x) {
        int r = (int)(idx / STATED), c = (int)(idx % STATED);
        out[idx] = (c < HIDD) ? hs[(size_t)r * HIDD + c] : ss[(size_t)r * STOCHD + (c - HIDD)];
    }
}

// ------------------------- loss reductions -------------------------
__global__ void zero_acc_k(double* acc) {
    if (threadIdx.x < 3) acc[threadIdx.x] = 0.0;
}

__global__ void kl_reduce_k(const float* __restrict__ praw, const float* __restrict__ qmu,
                            const float* __restrict__ qstd, double* __restrict__ acc)
{
    __shared__ double sh[256];
    double s = 0.0;
    long total = (long)TBD * STOCHD;
    for (long idx = blockIdx.x * (long)blockDim.x + threadIdx.x; idx < total;
         idx += (long)gridDim.x * blockDim.x) {
        int r = (int)(idx / STOCHD), i = (int)(idx % STOCHD);
        float pmu = praw[(size_t)r * 2 * STOCHD + i];
        float psd = softplusf(praw[(size_t)r * 2 * STOCHD + STOCHD + i]) + 1e-4f;
        float qm = qmu[idx], qs = qstd[idx];
        float d = qm - pmu;
        float kl = logf(psd / qs) + (qs * qs + d * d) / (2.f * psd * psd) - 0.5f;
        s += (double)kl;
    }
    sh[threadIdx.x] = s; __syncthreads();
    for (int o = 128; o > 0; o >>= 1) {
        if (threadIdx.x < o) sh[threadIdx.x] += sh[threadIdx.x + o];
        __syncthreads();
    }
    if (threadIdx.x == 0) atomicAdd(acc, sh[0]);
}

__global__ void emb_reduce_k(const float* __restrict__ emb, const float* __restrict__ embmu,
                             double* __restrict__ acc)
{
    __shared__ double sh[256];
    double s = 0.0;
    long total = (long)TBD * EMBD;
    for (long idx = blockIdx.x * (long)blockDim.x + threadIdx.x; idx < total;
         idx += (long)gridDim.x * blockDim.x) {
        float d = emb[idx] - embmu[idx];
        s += (double)(0.5f * d * d + 0.5f * LOG2PI_F);
    }
    sh[threadIdx.x] = s; __syncthreads();
    for (int o = 128; o > 0; o >>= 1) {
        if (threadIdx.x < o) sh[threadIdx.x] += sh[threadIdx.x + o];
        __syncthreads();
    }
    if (threadIdx.x == 0) atomicAdd(acc, sh[0]);
}

// reward head: mu = big2[r,:] . W[0,:] + b ; loss elem = 0.5*(reward-mu)^2 + 0.5*log2pi
__global__ void reward_reduce_k(const float* __restrict__ big2, const float* __restrict__ W,
                                const float* __restrict__ bias, const float* __restrict__ reward,
                                double* __restrict__ acc)
{
    __shared__ double sh[8];
    int lane = threadIdx.x & 31;
    int wid_in_block = threadIdx.x >> 5;
    int gwarp = (blockIdx.x * blockDim.x + threadIdx.x) >> 5;
    int nwarps = (gridDim.x * blockDim.x) >> 5;
    double local = 0.0;
    for (int r = gwarp; r < TBD; r += nwarps) {
        float sum = 0.f;
        const float* row = big2 + (size_t)r * FEATD;
        for (int k = lane; k < FEATD; k += 32) sum = fmaf(row[k], W[k], sum);
#pragma unroll
        for (int o = 16; o > 0; o >>= 1) sum += __shfl_xor_sync(0xffffffffu, sum, o);
        if (lane == 0) {
            float mu = sum + bias[0];
            float d = reward[r] - mu;
            local += (double)(0.5f * d * d + 0.5f * LOG2PI_F);
        }
    }
    if (lane == 0) sh[wid_in_block] = local;
    __syncthreads();
    if (threadIdx.x == 0) {
        double t = 0.0;
        for (int i = 0; i < (int)(blockDim.x >> 5); i++) t += sh[i];
        atomicAdd(acc, t);
    }
}

__global__ void finalize_k(const double* __restrict__ acc, float* __restrict__ out, int n) {
    double inv = 1.0 / (double)(TT * BB);
    float loss = (float)((acc[0] + acc[1] + acc[2]) * inv);
    for (int i = 0; i < n; i++) out[i] = loss;
}

// ------------------------- host -------------------------
static float* symaddr(const void* sym) {
    void* p = nullptr;
    cudaGetSymbolAddress(&p, sym);
    return (float*)p;
}

extern "C" void kernel_launch(void* const* d_in, const int* in_sizes, int n_in,
                              void* d_out, int out_size)
{
    const float* emb     = (const float*)d_in[0];
    const float* action  = (const float*)d_in[1];
    const float* reward  = (const float*)d_in[2];
    const float* eps     = (const float*)d_in[3];
    const float* gru_Wih = (const float*)d_in[4];
    const float* gru_bih = (const float*)d_in[5];
    const float* gru_Whh = (const float*)d_in[6];
    const float* gru_bhh = (const float*)d_in[7];
    const float* st_W0 = (const float*)d_in[8];  const float* st_b0 = (const float*)d_in[9];
    const float* st_W1 = (const float*)d_in[10]; const float* st_b1 = (const float*)d_in[11];
    const float* st_W2 = (const float*)d_in[12]; const float* st_b2 = (const float*)d_in[13];
    const float* ep_W0 = (const float*)d_in[14]; const float* ep_b0 = (const float*)d_in[15];
    const float* ep_W1 = (const float*)d_in[16]; const float* ep_b1 = (const float*)d_in[17];
    const float* ep_W2 = (const float*)d_in[18]; const float* ep_b2 = (const float*)d_in[19];
    const float* rp_W0 = (const float*)d_in[20]; const float* rp_b0 = (const float*)d_in[21];
    const float* rp_W1 = (const float*)d_in[22]; const float* rp_b1 = (const float*)d_in[23];
    const float* rp_W2 = (const float*)d_in[24]; const float* rp_b2 = (const float*)d_in[25];

    float* hs      = symaddr(g_hs);
    float* ss      = symaddr(g_ss);
    float* qmu     = symaddr(g_qmu);
    float* qstd    = symaddr(g_qstd);
    float* xcat    = symaddr(g_xcat);
    float* gi      = symaddr(g_gi);
    float* gh      = symaddr(g_gh);
    float* postcat = symaddr(g_postcat);
    float* h1      = symaddr(g_h1);
    float* h2      = symaddr(g_h2);
    float* qraw    = symaddr(g_qraw);
    float* zeros   = symaddr(g_zerobuf);
    float* part    = symaddr(g_part);
    float* prev    = symaddr(g_prev);
    float* states  = symaddr(g_states);
    float* big1    = symaddr(g_big1);
    float* big2    = symaddr(g_big2);
    float* preemb  = symaddr(g_preemb);
    float* priorin = symaddr(g_priorin);
    float* praw    = symaddr(g_praw);
    float* embmu   = symaddr(g_embmu);
    double* acc    = (double*)symaddr(g_acc);

    zero_acc_k<<<1, 32>>>(acc);

    // ---------------- sequential recurrence ----------------
    for (int t = 0; t < TT; t++) {
        const float* s_in = (t == 0) ? zeros : (ss + (size_t)(t - 1) * BB * STOCHD);
        const float* h_in = (t == 0) ? zeros : (hs + (size_t)(t - 1) * BB * HIDD);
        const float* e_prev = emb + (size_t)((t == 0) ? 0 : (t - 1)) * BB * EMBD;
        float* h_out = hs + (size_t)t * BB * HIDD;

        // x = concat(s, a)  [256, 70]
        concat2_k<<<70, 256>>>(s_in, STOCHD, action + (size_t)t * BB * ADIM, ADIM, xcat, BB);
        // gi = x @ Wih^T + bih   [256, 1536], K=70
        sgemm64<0><<<dim3(24, 4), 256>>>(xcat, gru_Wih, gru_bih, gi, BB, 3 * HIDD, STOCHD + ADIM);
        // gh = h @ Whh^T + bhh   [256, 1536], K=512, split-K 2
        sgemm64_part<<<dim3(24, 4, 2), 256>>>(h_in, gru_Whh, part, BB, 3 * HIDD, HIDD, 256);
        combine_k<0><<<1024, 256>>>(part, gru_bhh, gh, BB, 3 * HIDD, 2);
        // gates
        gru_gates_k<<<512, 256>>>(gi, gh, h_in, h_out);
        // posterior input: concat(next_h, emb_prev)  [256, 1536]
        concat2_k<<<1024, 256>>>(h_out, HIDD, e_prev, EMBD, postcat, BB);
        // st L0: [256,512] K=1536, split-K 8
        sgemm64_part<<<dim3(8, 4, 8), 256>>>(postcat, st_W0, part, BB, FEATD, HIDD + EMBD, 192);
        combine_k<1><<<512, 256>>>(part, st_b0, h1, BB, FEATD, 8);
        // st L1: [256,512] K=512, split-K 4
        sgemm64_part<<<dim3(8, 4, 4), 256>>>(h1, st_W1, part, BB, FEATD, FEATD, 128);
        combine_k<1><<<512, 256>>>(part, st_b1, h2, BB, FEATD, 4);
        // st L2: [256,128] K=512, split-K 8
        sgemm64_part<<<dim3(2, 4, 8), 256>>>(h2, st_W2, part, BB, 2 * STOCHD, FEATD, 64);
        combine_k<0><<<128, 256>>>(part, st_b2, qraw, BB, 2 * STOCHD, 8);
        // sample posterior
        sample_k<<<64, 256>>>(qraw, eps + (size_t)t * BB * STOCHD,
                              qmu + (size_t)t * BB * STOCHD, qstd + (size_t)t * BB * STOCHD,
                              ss + (size_t)t * BB * STOCHD);
    }

    // ---------------- batched prior path ----------------
    build_prev_k<<<2048, 256>>>(hs, ss, prev);
    // pre_emb = ep_mlp(prev_state)
    sgemm128<1><<<dim3(4, 128), 256>>>(prev, ep_W0, ep_b0, big1, TBD, FEATD, STATED);
    sgemm128<1><<<dim3(4, 128), 256>>>(big1, ep_W1, ep_b1, big2, TBD, FEATD, FEATD);
    sgemm128<0><<<dim3(8, 128), 256>>>(big2, ep_W2, ep_b2, preemb, TBD, EMBD, FEATD);
    // prior = st_mlp(concat(next_h, pre_emb))
    concat2_k<<<4096, 256>>>(hs, HIDD, preemb, EMBD, priorin, TBD);
    sgemm128<1><<<dim3(4, 128), 256>>>(priorin, st_W0, st_b0, big1, TBD, FEATD, HIDD + EMBD);
    sgemm128<1><<<dim3(4, 128), 256>>>(big1, st_W1, st_b1, big2, TBD, FEATD, FEATD);
    sgemm128<0><<<dim3(1, 128), 256>>>(big2, st_W2, st_b2, praw, TBD, 2 * STOCHD, FEATD);
    kl_reduce_k<<<1024, 256>>>(praw, qmu, qstd, acc + 0);

    // ---------------- emb / reward losses ----------------
    build_states_k<<<2048, 256>>>(hs, ss, states);
    sgemm128<1><<<dim3(4, 128), 256>>>(states, ep_W0, ep_b0, big1, TBD, FEATD, STATED);
    sgemm128<1><<<dim3(4, 128), 256>>>(big1, ep_W1, ep_b1, big2, TBD, FEATD, FEATD);
    sgemm128<0><<<dim3(8, 128), 256>>>(big2, ep_W2, ep_b2, embmu, TBD, EMBD, FEATD);
    emb_reduce_k<<<2048, 256>>>(emb, embmu, acc + 1);

    sgemm128<1><<<dim3(4, 128), 256>>>(states, rp_W0, rp_b0, big1, TBD, FEATD, STATED);
    sgemm128<1><<<dim3(4, 128), 256>>>(big1, rp_W1, rp_b1, big2, TBD, FEATD, FEATD);
    reward_reduce_k<<<512, 256>>>(big2, rp_W2, rp_b2, reward, acc + 2);

    finalize_k<<<1, 1>>>(acc, (float*)d_out, out_size);
}